// round 13
// baseline (speedup 1.0000x reference)
#include <cuda_runtime.h>
#include <cuda_bf16.h>
#include <cuda_fp16.h>
#include <stdint.h>

#define BB 512
#define TT 256
#define HH 256
#define HORZ 22
#define RPB 4          // batch rows per CTA
#define NTH 256        // one thread per hidden column
#define NCTA (BB / RPB)

#define SCL  16.0f
#define ISCL 0.0625f

// dynamic smem layout (bytes)
#define OFF_WZR 0          // u32 [128kp][256col] : e4m3x4 (uz,ur)k0 | (uz,ur)k1<<16, x16 scale = 131072
#define OFF_UH  131072     // u32 [64kq][256col]  : e4m3x4 uh[4kq..4kq+3] x16 = 65536
#define OFF_HT  196608     // f16 [256k][4r] = 2048
#define OFF_RHT 198656     // f16 [256k][4r] = 2048
#define OFF_XST 200704     // f32 [256t][4r] = 4096
#define OFF_WV  204800     // f32 [8][256]   = 8192
#define SMEM_BYTES 212992

__device__ float g_h[BB * HH];   // final hidden state scratch

__device__ __forceinline__ float ftanha(float x) {
    float y; asm("tanh.approx.f32 %0, %1;" : "=f"(y) : "f"(x)); return y;
}
__device__ __forceinline__ float fsig(float x) {
    return fmaf(0.5f, ftanha(0.5f * x), 0.5f);
}
__device__ __forceinline__ uint32_t s2u(const void* p) {
    return (uint32_t)__cvta_generic_to_shared(p);
}
__device__ __forceinline__ __half2 u2h(uint32_t u) {
    __half2 h; *reinterpret_cast<uint32_t*>(&h) = u; return h;
}
__device__ __forceinline__ uint32_t h2u(__half2 h) {
    return *reinterpret_cast<uint32_t*>(&h);
}
// split u32 of e4m3x4 into two f16x2 words
__device__ __forceinline__ void f8x4_to_2h2(uint32_t w, uint32_t& lo, uint32_t& hi) {
    asm("{.reg .b16 l,h;\n\t"
        "mov.b32 {l,h}, %2;\n\t"
        "cvt.rn.f16x2.e4m3x2 %0, l;\n\t"
        "cvt.rn.f16x2.e4m3x2 %1, h;}"
        : "=r"(lo), "=r"(hi) : "r"(w));
}
__device__ __forceinline__ float2 h2f(uint32_t p) {   // f16x2 -> (f32 lo, f32 hi)
    float2 f;
    asm("{.reg .b16 l,h; mov.b32 {l,h}, %2; cvt.f32.f16 %0, l; cvt.f32.f16 %1, h;}"
        : "=f"(f.x), "=f"(f.y) : "r"(p));
    return f;
}
__device__ __forceinline__ uint32_t f2h2(float lo, float hi) {   // pack (lo,hi) f16x2
    uint32_t d; asm("cvt.rn.f16x2.f32 %0, %1, %2;" : "=r"(d) : "f"(hi), "f"(lo)); return d;
}
__device__ __forceinline__ uint16_t f2e8x2(float lo, float hi) { // pack e4m3x2
    uint16_t d; asm("cvt.rn.satfinite.e4m3x2.f32 %0, %1, %2;" : "=h"(d) : "f"(hi), "f"(lo));
    return d;
}
__device__ __forceinline__ void sts32(uint32_t a, uint32_t v) {
    asm volatile("st.shared.b32 [%0], %1;" :: "r"(a), "r"(v));
}

extern "C" __global__ __launch_bounds__(NTH, 1)
void garch_gru_recur(const float* __restrict__ x,
                     const float* __restrict__ Wzw, const float* __restrict__ Wzb,
                     const float* __restrict__ Uzw, const float* __restrict__ Uzb,
                     const float* __restrict__ Wrw, const float* __restrict__ Wrb,
                     const float* __restrict__ Urw, const float* __restrict__ Urb,
                     const float* __restrict__ Whw, const float* __restrict__ Whb,
                     const float* __restrict__ Uhw, const float* __restrict__ Uhb,
                     const float* __restrict__ Wgw, const float* __restrict__ Wgb,
                     const float* __restrict__ omega_raw, const float* __restrict__ alpha_raw,
                     const float* __restrict__ beta_raw,  const float* __restrict__ gamma_p,
                     float* __restrict__ sig_out)
{
    extern __shared__ char smem[];
    float* xsT = (float*)(smem + OFF_XST);
    float* wv  = (float*)(smem + OFF_WV);

    const int tid = threadIdx.x;
    const int col = tid;                       // hidden column owned
    const int rbase = (int)blockIdx.x * RPB;   // batch rows of this CTA

    const uint32_t smem_u = s2u(smem);
    const uint32_t wzr2_base = smem_u + OFF_WZR + col * 4;  // + kp*1024
    const uint32_t uh2_base  = smem_u + OFF_UH  + col * 4;  // + kq*1024
    const uint32_t ht_base   = smem_u + OFF_HT;             // + k*8 (v4 = 2 k)
    const uint32_t rht_base  = smem_u + OFF_RHT;            // + kp*16 (v4 = 2 k)
    const uint32_t ht_own    = smem_u + OFF_HT  + col * 8;
    const uint32_t rht_own   = smem_u + OFF_RHT + col * 8;
    const uint32_t xs_base   = smem_u + OFF_XST;

    // ---- preamble: convert weights to packed e4m3 words (scaled x16) ----
    #pragma unroll 4
    for (int kp = 0; kp < HH / 2; kp++) {
        const int k0 = 2 * kp;
        const uint16_t p0 = f2e8x2(Uzw[k0 * HH + col] * SCL, Urw[k0 * HH + col] * SCL);
        const uint16_t p1 = f2e8x2(Uzw[(k0+1) * HH + col] * SCL, Urw[(k0+1) * HH + col] * SCL);
        sts32(wzr2_base + kp * 1024, (uint32_t)p0 | ((uint32_t)p1 << 16));
    }
    #pragma unroll 4
    for (int kq = 0; kq < HH / 4; kq++) {
        const int k0 = 4 * kq;
        const uint16_t p0 = f2e8x2(Uhw[k0 * HH + col] * SCL, Uhw[(k0+1) * HH + col] * SCL);
        const uint16_t p1 = f2e8x2(Uhw[(k0+2) * HH + col] * SCL, Uhw[(k0+3) * HH + col] * SCL);
        sts32(uh2_base + kq * 1024, (uint32_t)p0 | ((uint32_t)p1 << 16));
    }
    {   // per-column scalars (fp32)
        wv[0*HH+col] = Wzw[col];
        wv[1*HH+col] = Wzb[col] + Uzb[col];
        wv[2*HH+col] = Wrw[col];
        wv[3*HH+col] = Wrb[col] + Urb[col];
        wv[4*HH+col] = Whw[col];
        wv[5*HH+col] = Whb[col] + Uhb[col];
        wv[6*HH+col] = Wgw[col];
        wv[7*HH+col] = Wgb[col];
    }
    // x tile (fp32, exact: feeds GARCH)
    for (int idx = tid; idx < RPB * TT; idx += NTH) {
        int r = idx >> 8, t = idx & (TT - 1);
        xsT[t * RPB + r] = x[(rbase + r) * TT + t];
    }
    // zero h (f16)
    asm volatile("st.shared.v2.b32 [%0], {%1,%1};" :: "r"(ht_own), "r"(0u));
    __syncthreads();

    // ---- per-thread constants ----
    const float wzc = wv[0*HH+col], bzc = wv[1*HH+col];
    const float wrc = wv[2*HH+col], brc = wv[3*HH+col];
    const float whc = wv[4*HH+col], bhc = wv[5*HH+col];
    const float wgc = wv[6*HH+col], wgbc= wv[7*HH+col];
    const float gamma = gamma_p[0];

    // GARCH scalar params (exact fp32; replicated on all threads)
    const float orw = omega_raw[0];
    const float om = ((orw > 20.0f) ? orw : log1pf(expf(orw))) + 1e-6f;
    const float av = 1.0f / (1.0f + expf(-alpha_raw[0]));
    const float bv = (1.0f / (1.0f + expf(-beta_raw[0]))) * (1.0f - av * 0.99f);
    float4 es = make_float4(1e-6f, 1e-6f, 1e-6f, 1e-6f);
    float4 ss = es;

    // own h kept in fp32 registers
    float h0 = 0.0f, h1 = 0.0f, h2 = 0.0f, h3 = 0.0f;

    const __half2 hzero = __float2half2_rn(0.0f);

    for (int t = 0; t < TT; t++) {
        float4 xv;
        asm("ld.shared.v4.f32 {%0,%1,%2,%3}, [%4];"
            : "=f"(xv.x), "=f"(xv.y), "=f"(xv.z), "=f"(xv.w)
            : "r"(xs_base + t * 16));

        // ---- phase A: z and r gates; 2 k per iter, packed loads ----
        // dup+fma written with half2 intrinsics so ptxas can fold the
        // broadcast into HFMA2 half-lane selectors (.H0_H0/.H1_H1).
        __half2 az01 = hzero, az23 = hzero, ar01 = hzero, ar23 = hzero;
        #pragma unroll 8
        for (int kp = 0; kp < HH / 2; kp++) {
            uint32_t g01au, g23au, g01bu, g23bu;
            asm("ld.shared.v4.b32 {%0,%1,%2,%3}, [%4];"
                : "=r"(g01au), "=r"(g23au), "=r"(g01bu), "=r"(g23bu)
                : "r"(ht_base + kp * 16));              // h for k=2kp and 2kp+1 (broadcast)
            uint32_t w2;
            asm("ld.shared.b32 %0, [%1];" : "=r"(w2) : "r"(wzr2_base + kp * 1024));
            uint32_t wAu, wBu;
            f8x4_to_2h2(w2, wAu, wBu);                  // (uz,ur) for k0 and k1
            const __half2 wA = u2h(wAu), wB = u2h(wBu);
            const __half2 g01a = u2h(g01au), g23a = u2h(g23au);
            const __half2 g01b = u2h(g01bu), g23b = u2h(g23bu);
            const __half2 z2a = __half2half2(__low2half(wA));
            const __half2 r2a = __half2half2(__high2half(wA));
            const __half2 z2b = __half2half2(__low2half(wB));
            const __half2 r2b = __half2half2(__high2half(wB));
            az01 = __hfma2(g01a, z2a, az01); az23 = __hfma2(g23a, z2a, az23);
            ar01 = __hfma2(g01a, r2a, ar01); ar23 = __hfma2(g23a, r2a, ar23);
            az01 = __hfma2(g01b, z2b, az01); az23 = __hfma2(g23b, z2b, az23);
            ar01 = __hfma2(g01b, r2b, ar01); ar23 = __hfma2(g23b, r2b, ar23);
        }
        const float2 a0 = h2f(h2u(az01)), a1 = h2f(h2u(az23));
        const float2 b0 = h2f(h2u(ar01)), b1 = h2f(h2u(ar23));
        const float z0 = fsig(fmaf(a0.x, ISCL, fmaf(xv.x, wzc, bzc)));
        const float z1 = fsig(fmaf(a0.y, ISCL, fmaf(xv.y, wzc, bzc)));
        const float z2v= fsig(fmaf(a1.x, ISCL, fmaf(xv.z, wzc, bzc)));
        const float z3 = fsig(fmaf(a1.y, ISCL, fmaf(xv.w, wzc, bzc)));
        const float rh0 = fsig(fmaf(b0.x, ISCL, fmaf(xv.x, wrc, brc))) * h0;
        const float rh1 = fsig(fmaf(b0.y, ISCL, fmaf(xv.y, wrc, brc))) * h1;
        const float rh2 = fsig(fmaf(b1.x, ISCL, fmaf(xv.z, wrc, brc))) * h2;
        const float rh3 = fsig(fmaf(b1.y, ISCL, fmaf(xv.w, wrc, brc))) * h3;
        {
            const uint32_t p01 = f2h2(rh0, rh1), p23 = f2h2(rh2, rh3);
            asm volatile("st.shared.v2.b32 [%0], {%1,%2};"
                         :: "r"(rht_own), "r"(p01), "r"(p23));
        }

        // independent work before the barrier: GARCH + gt + z*h_old
        float4 g;
        g.x = fmaf(av, es.x, fmaf(bv, ss.x, om));
        g.y = fmaf(av, es.y, fmaf(bv, ss.y, om));
        g.z = fmaf(av, es.z, fmaf(bv, ss.z, om));
        g.w = fmaf(av, es.w, fmaf(bv, ss.w, om));
        es = make_float4(xv.x*xv.x, xv.y*xv.y, xv.z*xv.z, xv.w*xv.w);
        ss = g;
        const float gt0 = fmaf(g.x, wgc, wgbc), gt1 = fmaf(g.y, wgc, wgbc);
        const float gt2 = fmaf(g.z, wgc, wgbc), gt3 = fmaf(g.w, wgc, wgbc);
        const float zh0 = z0 * h0, zh1 = z1 * h1, zh2 = z2v * h2, zh3 = z3 * h3;
        __syncthreads();   // r*h tile complete

        // ---- phase B: h_tilde; 4 k per iter, packed loads ----
        __half2 ah01 = hzero, ah23 = hzero;
        #pragma unroll 8
        for (int kq = 0; kq < HH / 4; kq++) {
            uint32_t ra01u, ra23u, rb01u, rb23u, rc01u, rc23u, rd01u, rd23u;
            asm("ld.shared.v4.b32 {%0,%1,%2,%3}, [%4];"
                : "=r"(ra01u), "=r"(ra23u), "=r"(rb01u), "=r"(rb23u)
                : "r"(rht_base + kq * 32));             // rh for k=4kq, 4kq+1
            asm("ld.shared.v4.b32 {%0,%1,%2,%3}, [%4];"
                : "=r"(rc01u), "=r"(rc23u), "=r"(rd01u), "=r"(rd23u)
                : "r"(rht_base + kq * 32 + 16));        // rh for k=4kq+2, 4kq+3
            uint32_t u2;
            asm("ld.shared.b32 %0, [%1];" : "=r"(u2) : "r"(uh2_base + kq * 1024));
            uint32_t uAu, uBu;
            f8x4_to_2h2(u2, uAu, uBu);                  // (uh_k0,uh_k1), (uh_k2,uh_k3)
            const __half2 uA = u2h(uAu), uB = u2h(uBu);
            const __half2 uloA = __half2half2(__low2half(uA));
            const __half2 uhiA = __half2half2(__high2half(uA));
            const __half2 uloB = __half2half2(__low2half(uB));
            const __half2 uhiB = __half2half2(__high2half(uB));
            ah01 = __hfma2(u2h(ra01u), uloA, ah01); ah23 = __hfma2(u2h(ra23u), uloA, ah23);
            ah01 = __hfma2(u2h(rb01u), uhiA, ah01); ah23 = __hfma2(u2h(rb23u), uhiA, ah23);
            ah01 = __hfma2(u2h(rc01u), uloB, ah01); ah23 = __hfma2(u2h(rc23u), uloB, ah23);
            ah01 = __hfma2(u2h(rd01u), uhiB, ah01); ah23 = __hfma2(u2h(rd23u), uhiB, ah23);
        }
        const float2 c0 = h2f(h2u(ah01)), c1 = h2f(h2u(ah23));
        const float t0 = ftanha(fmaf(c0.x, ISCL, fmaf(xv.x, whc, bhc)));
        const float t1 = ftanha(fmaf(c0.y, ISCL, fmaf(xv.y, whc, bhc)));
        const float t2 = ftanha(fmaf(c1.x, ISCL, fmaf(xv.z, whc, bhc)));
        const float t3 = ftanha(fmaf(c1.y, ISCL, fmaf(xv.w, whc, bhc)));
        h0 = ftanha(fmaf(gamma, gt0, fmaf(-z0, t0, t0) + zh0));
        h1 = ftanha(fmaf(gamma, gt1, fmaf(-z1, t1, t1) + zh1));
        h2 = ftanha(fmaf(gamma, gt2, fmaf(-z2v, t2, t2) + zh2));
        h3 = ftanha(fmaf(gamma, gt3, fmaf(-z3, t3, t3) + zh3));
        {
            const uint32_t p01 = f2h2(h0, h1), p23 = f2h2(h2, h3);
            asm volatile("st.shared.v2.b32 [%0], {%1,%2};"
                         :: "r"(ht_own), "r"(p01), "r"(p23));
        }
        __syncthreads();   // h tile complete -> next step
    }

    // sigma_sq output (exact fp32 path)
    if (tid == 0) {
        sig_out[rbase + 0] = ss.x;
        sig_out[rbase + 1] = ss.y;
        sig_out[rbase + 2] = ss.z;
        sig_out[rbase + 3] = ss.w;
    }
    // final h (fp32 registers; coalesced across lanes)
    g_h[(rbase + 0) * HH + col] = h0;
    g_h[(rbase + 1) * HH + col] = h1;
    g_h[(rbase + 2) * HH + col] = h2;
    g_h[(rbase + 3) * HH + col] = h3;
}

// ---- final head: hid = relu(h@fc1+b); vol = clip(vol_base*(1+softplus(hid@fc2+b))) ----
extern "C" __global__ __launch_bounds__(256)
void garch_gru_head(const float* __restrict__ fc1w, const float* __restrict__ fc1b,
                    const float* __restrict__ fc2w, const float* __restrict__ fc2b,
                    float* __restrict__ out, int sig_off)
{
    __shared__ float hs[HH];
    __shared__ float hid[HH];
    const int row = blockIdx.x;
    const int tid = threadIdx.x;
    hs[tid] = g_h[row * HH + tid];
    __syncthreads();
    float acc = fc1b[tid];
    #pragma unroll 8
    for (int k = 0; k < HH; k++) acc = fmaf(hs[k], fc1w[k * HH + tid], acc);
    hid[tid] = fmaxf(acc, 0.0f);
    __syncthreads();
    if (tid < HORZ) {
        float u = fc2b[tid];
        #pragma unroll 8
        for (int j = 0; j < HH; j++) u = fmaf(hid[j], fc2w[j * HORZ + tid], u);
        const float sp = (u > 20.0f) ? u : log1pf(expf(u));
        const float ssq = out[sig_off + row];
        const float vb = sqrtf(ssq + 1e-8f);
        float v = vb * (1.0f + sp);
        v = fminf(fmaxf(v, 0.01f), 10.0f);
        out[row * HORZ + tid] = v;
    }
}

extern "C" void kernel_launch(void* const* d_in, const int* in_sizes, int n_in,
                              void* d_out, int out_size) {
    const float* x    = (const float*)d_in[0];
    const float* Wzw  = (const float*)d_in[1];
    const float* Wzb  = (const float*)d_in[2];
    const float* Uzw  = (const float*)d_in[3];
    const float* Uzb  = (const float*)d_in[4];
    const float* Wrw  = (const float*)d_in[5];
    const float* Wrb  = (const float*)d_in[6];
    const float* Urw  = (const float*)d_in[7];
    const float* Urb  = (const float*)d_in[8];
    const float* Whw  = (const float*)d_in[9];
    const float* Whb  = (const float*)d_in[10];
    const float* Uhw  = (const float*)d_in[11];
    const float* Uhb  = (const float*)d_in[12];
    const float* Wgw  = (const float*)d_in[13];
    const float* Wgb  = (const float*)d_in[14];
    const float* omr  = (const float*)d_in[15];
    const float* alr  = (const float*)d_in[16];
    const float* ber  = (const float*)d_in[17];
    const float* gam  = (const float*)d_in[18];
    const float* fc1w = (const float*)d_in[19];
    const float* fc1b = (const float*)d_in[20];
    const float* fc2w = (const float*)d_in[21];
    const float* fc2b = (const float*)d_in[22];
    float* out = (float*)d_out;
    const int sig_off = out_size - BB;   // vol[B,HOR] then sigma_sq[B]

    cudaFuncSetAttribute(garch_gru_recur,
                         cudaFuncAttributeMaxDynamicSharedMemorySize, SMEM_BYTES);
    garch_gru_recur<<<NCTA, NTH, SMEM_BYTES>>>(
        x, Wzw, Wzb, Uzw, Uzb, Wrw, Wrb, Urw, Urb, Whw, Whb, Uhw, Uhb, Wgw, Wgb,
        omr, alr, ber, gam, out + sig_off);
    garch_gru_head<<<BB, 256>>>(fc1w, fc1b, fc2w, fc2b, out, sig_off);
}

// round 16
// speedup vs baseline: 1.5241x; 1.5241x over previous
#include <cuda_runtime.h>
#include <cuda_bf16.h>
#include <stdint.h>

#define BB 512
#define TT 256
#define HH 256
#define HORZ 22
#define RPB 4          // batch rows per CTA
#define NTH 256        // one thread per hidden column
#define NCTA (BB / RPB)

#define SCL  16.0f
#define ISCL 0.0625f

// dynamic smem layout (bytes)
#define OFF_WZR 0          // u32 [128kp][256col] : e4m3x4 (uz,ur)k0 | (uz,ur)k1<<16, x16 scale = 131072
#define OFF_UH  131072     // u32 [64kq][256col]  : e4m3x4 uh[4kq..4kq+3] x16 = 65536
#define OFF_HT  196608     // f16 [256k][4r] = 2048
#define OFF_RHT 198656     // f16 [256k][4r] = 2048
#define OFF_XST 200704     // f32 [256t][4r] = 4096   (reused post-loop: f32 h [4r][256col])
#define OFF_WV  204800     // f32 [8][256]   = 8192   (reused post-loop: f32 hid [4r][256col])
#define SMEM_BYTES 212992

__device__ __forceinline__ float ftanha(float x) {
    float y; asm("tanh.approx.f32 %0, %1;" : "=f"(y) : "f"(x)); return y;
}
__device__ __forceinline__ float fsig(float x) {
    return fmaf(0.5f, ftanha(0.5f * x), 0.5f);
}
__device__ __forceinline__ uint32_t s2u(const void* p) {
    return (uint32_t)__cvta_generic_to_shared(p);
}
__device__ __forceinline__ void hfma2(uint32_t& d, uint32_t a, uint32_t b) {
    asm("fma.rn.f16x2 %0, %1, %2, %0;" : "+r"(d) : "r"(a), "r"(b));
}
__device__ __forceinline__ uint32_t dup_lo(uint32_t a) {
    uint32_t d; asm("prmt.b32 %0, %1, %1, 0x1010;" : "=r"(d) : "r"(a)); return d;
}
__device__ __forceinline__ uint32_t dup_hi(uint32_t a) {
    uint32_t d; asm("prmt.b32 %0, %1, %1, 0x3232;" : "=r"(d) : "r"(a)); return d;
}
// split u32 of e4m3x4 into two f16x2 words
__device__ __forceinline__ void f8x4_to_2h2(uint32_t w, uint32_t& lo, uint32_t& hi) {
    asm("{.reg .b16 l,h;\n\t"
        "mov.b32 {l,h}, %2;\n\t"
        "cvt.rn.f16x2.e4m3x2 %0, l;\n\t"
        "cvt.rn.f16x2.e4m3x2 %1, h;}"
        : "=r"(lo), "=r"(hi) : "r"(w));
}
__device__ __forceinline__ float2 h2f(uint32_t p) {   // f16x2 -> (f32 lo, f32 hi)
    float2 f;
    asm("{.reg .b16 l,h; mov.b32 {l,h}, %2; cvt.f32.f16 %0, l; cvt.f32.f16 %1, h;}"
        : "=f"(f.x), "=f"(f.y) : "r"(p));
    return f;
}
__device__ __forceinline__ uint32_t f2h2(float lo, float hi) {   // pack (lo,hi) f16x2
    uint32_t d; asm("cvt.rn.f16x2.f32 %0, %1, %2;" : "=r"(d) : "f"(hi), "f"(lo)); return d;
}
__device__ __forceinline__ uint16_t f2e8x2(float lo, float hi) { // pack e4m3x2
    uint16_t d; asm("cvt.rn.satfinite.e4m3x2.f32 %0, %1, %2;" : "=h"(d) : "f"(hi), "f"(lo));
    return d;
}
__device__ __forceinline__ void sts32(uint32_t a, uint32_t v) {
    asm volatile("st.shared.b32 [%0], %1;" :: "r"(a), "r"(v));
}

extern "C" __global__ __launch_bounds__(NTH, 1)
void garch_gru_fused(const float* __restrict__ x,
                     const float* __restrict__ Wzw, const float* __restrict__ Wzb,
                     const float* __restrict__ Uzw, const float* __restrict__ Uzb,
                     const float* __restrict__ Wrw, const float* __restrict__ Wrb,
                     const float* __restrict__ Urw, const float* __restrict__ Urb,
                     const float* __restrict__ Whw, const float* __restrict__ Whb,
                     const float* __restrict__ Uhw, const float* __restrict__ Uhb,
                     const float* __restrict__ Wgw, const float* __restrict__ Wgb,
                     const float* __restrict__ omega_raw, const float* __restrict__ alpha_raw,
                     const float* __restrict__ beta_raw,  const float* __restrict__ gamma_p,
                     const float* __restrict__ fc1w, const float* __restrict__ fc1b,
                     const float* __restrict__ fc2w, const float* __restrict__ fc2b,
                     float* __restrict__ out, int sig_off)
{
    extern __shared__ char smem[];
    float* xsT = (float*)(smem + OFF_XST);
    float* wv  = (float*)(smem + OFF_WV);

    const int tid = threadIdx.x;
    const int col = tid;                       // hidden column owned
    const int rbase = (int)blockIdx.x * RPB;   // batch rows of this CTA

    const uint32_t smem_u = s2u(smem);
    const uint32_t wzr2_base = smem_u + OFF_WZR + col * 4;  // + kp*1024
    const uint32_t uh2_base  = smem_u + OFF_UH  + col * 4;  // + kq*1024
    const uint32_t ht_base   = smem_u + OFF_HT;             // + k*8 (v4 = 2 k)
    const uint32_t rht_base  = smem_u + OFF_RHT;            // + kp*16 (v4 = 2 k)
    const uint32_t ht_own    = smem_u + OFF_HT  + col * 8;
    const uint32_t rht_own   = smem_u + OFF_RHT + col * 8;
    const uint32_t xs_base   = smem_u + OFF_XST;

    // ---- preamble: convert weights to packed e4m3 words (scaled x16) ----
    #pragma unroll 4
    for (int kp = 0; kp < HH / 2; kp++) {
        const int k0 = 2 * kp;
        const uint16_t p0 = f2e8x2(Uzw[k0 * HH + col] * SCL, Urw[k0 * HH + col] * SCL);
        const uint16_t p1 = f2e8x2(Uzw[(k0+1) * HH + col] * SCL, Urw[(k0+1) * HH + col] * SCL);
        sts32(wzr2_base + kp * 1024, (uint32_t)p0 | ((uint32_t)p1 << 16));
    }
    #pragma unroll 4
    for (int kq = 0; kq < HH / 4; kq++) {
        const int k0 = 4 * kq;
        const uint16_t p0 = f2e8x2(Uhw[k0 * HH + col] * SCL, Uhw[(k0+1) * HH + col] * SCL);
        const uint16_t p1 = f2e8x2(Uhw[(k0+2) * HH + col] * SCL, Uhw[(k0+3) * HH + col] * SCL);
        sts32(uh2_base + kq * 1024, (uint32_t)p0 | ((uint32_t)p1 << 16));
    }
    {   // per-column scalars (fp32)
        wv[0*HH+col] = Wzw[col];
        wv[1*HH+col] = Wzb[col] + Uzb[col];
        wv[2*HH+col] = Wrw[col];
        wv[3*HH+col] = Wrb[col] + Urb[col];
        wv[4*HH+col] = Whw[col];
        wv[5*HH+col] = Whb[col] + Uhb[col];
        wv[6*HH+col] = Wgw[col];
        wv[7*HH+col] = Wgb[col];
    }
    // x tile (fp32, exact: feeds GARCH)
    for (int idx = tid; idx < RPB * TT; idx += NTH) {
        int r = idx >> 8, t = idx & (TT - 1);
        xsT[t * RPB + r] = x[(rbase + r) * TT + t];
    }
    // zero h (f16)
    asm volatile("st.shared.v2.b32 [%0], {%1,%1};" :: "r"(ht_own), "r"(0u));
    __syncthreads();

    // ---- per-thread constants ----
    const float wzc = wv[0*HH+col], bzc = wv[1*HH+col];
    const float wrc = wv[2*HH+col], brc = wv[3*HH+col];
    const float whc = wv[4*HH+col], bhc = wv[5*HH+col];
    const float wgc = wv[6*HH+col], wgbc= wv[7*HH+col];
    const float gamma = gamma_p[0];

    // GARCH scalar params (exact fp32; replicated on all threads)
    const float orw = omega_raw[0];
    const float om = ((orw > 20.0f) ? orw : log1pf(expf(orw))) + 1e-6f;
    const float av = 1.0f / (1.0f + expf(-alpha_raw[0]));
    const float bv = (1.0f / (1.0f + expf(-beta_raw[0]))) * (1.0f - av * 0.99f);
    float4 es = make_float4(1e-6f, 1e-6f, 1e-6f, 1e-6f);
    float4 ss = es;

    // own h kept in fp32 registers
    float h0 = 0.0f, h1 = 0.0f, h2 = 0.0f, h3 = 0.0f;

    for (int t = 0; t < TT; t++) {
        float4 xv;
        asm("ld.shared.v4.f32 {%0,%1,%2,%3}, [%4];"
            : "=f"(xv.x), "=f"(xv.y), "=f"(xv.z), "=f"(xv.w)
            : "r"(xs_base + t * 16));

        // hoisted loop-independent work: x-projections, GARCH update, gt
        const float xz0 = fmaf(xv.x, wzc, bzc), xz1 = fmaf(xv.y, wzc, bzc);
        const float xz2 = fmaf(xv.z, wzc, bzc), xz3 = fmaf(xv.w, wzc, bzc);
        const float xr0 = fmaf(xv.x, wrc, brc), xr1 = fmaf(xv.y, wrc, brc);
        const float xr2 = fmaf(xv.z, wrc, brc), xr3 = fmaf(xv.w, wrc, brc);
        const float xh0 = fmaf(xv.x, whc, bhc), xh1 = fmaf(xv.y, whc, bhc);
        const float xh2 = fmaf(xv.z, whc, bhc), xh3 = fmaf(xv.w, whc, bhc);
        float4 g;
        g.x = fmaf(av, es.x, fmaf(bv, ss.x, om));
        g.y = fmaf(av, es.y, fmaf(bv, ss.y, om));
        g.z = fmaf(av, es.z, fmaf(bv, ss.z, om));
        g.w = fmaf(av, es.w, fmaf(bv, ss.w, om));
        es = make_float4(xv.x*xv.x, xv.y*xv.y, xv.z*xv.z, xv.w*xv.w);
        ss = g;
        const float gt0 = fmaf(g.x, wgc, wgbc), gt1 = fmaf(g.y, wgc, wgbc);
        const float gt2 = fmaf(g.z, wgc, wgbc), gt3 = fmaf(g.w, wgc, wgbc);

        // ---- phase A: z and r gates; 2 k per iter, packed loads ----
        uint32_t az01 = 0u, az23 = 0u, ar01 = 0u, ar23 = 0u;
        #pragma unroll 8
        for (int kp = 0; kp < HH / 2; kp++) {
            uint32_t g01a, g23a, g01b, g23b;
            asm("ld.shared.v4.b32 {%0,%1,%2,%3}, [%4];"
                : "=r"(g01a), "=r"(g23a), "=r"(g01b), "=r"(g23b)
                : "r"(ht_base + kp * 16));              // h for k=2kp and 2kp+1 (broadcast)
            uint32_t w2;
            asm("ld.shared.b32 %0, [%1];" : "=r"(w2) : "r"(wzr2_base + kp * 1024));
            uint32_t wA, wB;
            f8x4_to_2h2(w2, wA, wB);                    // (uz,ur) for k0 and k1
            const uint32_t z2a = dup_lo(wA), r2a = dup_hi(wA);
            const uint32_t z2b = dup_lo(wB), r2b = dup_hi(wB);
            hfma2(az01, g01a, z2a); hfma2(az23, g23a, z2a);
            hfma2(ar01, g01a, r2a); hfma2(ar23, g23a, r2a);
            hfma2(az01, g01b, z2b); hfma2(az23, g23b, z2b);
            hfma2(ar01, g01b, r2b); hfma2(ar23, g23b, r2b);
        }
        const float2 a0 = h2f(az01), a1 = h2f(az23);
        const float2 b0 = h2f(ar01), b1 = h2f(ar23);
        const float z0 = fsig(fmaf(a0.x, ISCL, xz0));
        const float z1 = fsig(fmaf(a0.y, ISCL, xz1));
        const float z2v= fsig(fmaf(a1.x, ISCL, xz2));
        const float z3 = fsig(fmaf(a1.y, ISCL, xz3));
        const float rh0 = fsig(fmaf(b0.x, ISCL, xr0)) * h0;
        const float rh1 = fsig(fmaf(b0.y, ISCL, xr1)) * h1;
        const float rh2 = fsig(fmaf(b1.x, ISCL, xr2)) * h2;
        const float rh3 = fsig(fmaf(b1.y, ISCL, xr3)) * h3;
        {
            const uint32_t p01 = f2h2(rh0, rh1), p23 = f2h2(rh2, rh3);
            asm volatile("st.shared.v2.b32 [%0], {%1,%2};"
                         :: "r"(rht_own), "r"(p01), "r"(p23));
        }
        const float zh0 = z0 * h0, zh1 = z1 * h1, zh2 = z2v * h2, zh3 = z3 * h3;
        __syncthreads();   // r*h tile complete

        // ---- phase B: h_tilde; 4 k per iter, packed loads ----
        uint32_t ah01 = 0u, ah23 = 0u;
        #pragma unroll 8
        for (int kq = 0; kq < HH / 4; kq++) {
            uint32_t ra01, ra23, rb01, rb23, rc01, rc23, rd01, rd23;
            asm("ld.shared.v4.b32 {%0,%1,%2,%3}, [%4];"
                : "=r"(ra01), "=r"(ra23), "=r"(rb01), "=r"(rb23)
                : "r"(rht_base + kq * 32));             // rh for k=4kq, 4kq+1
            asm("ld.shared.v4.b32 {%0,%1,%2,%3}, [%4];"
                : "=r"(rc01), "=r"(rc23), "=r"(rd01), "=r"(rd23)
                : "r"(rht_base + kq * 32 + 16));        // rh for k=4kq+2, 4kq+3
            uint32_t u2;
            asm("ld.shared.b32 %0, [%1];" : "=r"(u2) : "r"(uh2_base + kq * 1024));
            uint32_t uA, uB;
            f8x4_to_2h2(u2, uA, uB);                    // (uh_k0,uh_k1), (uh_k2,uh_k3)
            const uint32_t uloA = dup_lo(uA), uhiA = dup_hi(uA);
            const uint32_t uloB = dup_lo(uB), uhiB = dup_hi(uB);
            hfma2(ah01, ra01, uloA); hfma2(ah23, ra23, uloA);
            hfma2(ah01, rb01, uhiA); hfma2(ah23, rb23, uhiA);
            hfma2(ah01, rc01, uloB); hfma2(ah23, rc23, uloB);
            hfma2(ah01, rd01, uhiB); hfma2(ah23, rd23, uhiB);
        }
        const float2 c0 = h2f(ah01), c1 = h2f(ah23);
        const float t0 = ftanha(fmaf(c0.x, ISCL, xh0));
        const float t1 = ftanha(fmaf(c0.y, ISCL, xh1));
        const float t2 = ftanha(fmaf(c1.x, ISCL, xh2));
        const float t3 = ftanha(fmaf(c1.y, ISCL, xh3));
        h0 = ftanha(fmaf(gamma, gt0, fmaf(-z0, t0, t0) + zh0));
        h1 = ftanha(fmaf(gamma, gt1, fmaf(-z1, t1, t1) + zh1));
        h2 = ftanha(fmaf(gamma, gt2, fmaf(-z2v, t2, t2) + zh2));
        h3 = ftanha(fmaf(gamma, gt3, fmaf(-z3, t3, t3) + zh3));
        {
            const uint32_t p01 = f2h2(h0, h1), p23 = f2h2(h2, h3);
            asm volatile("st.shared.v2.b32 [%0], {%1,%2};"
                         :: "r"(ht_own), "r"(p01), "r"(p23));
        }
        __syncthreads();   // h tile complete -> next step
    }

    // ================= fused head =================
    // sigma_sq output (exact fp32 path)
    if (tid == 0) {
        out[sig_off + rbase + 0] = ss.x;
        out[sig_off + rbase + 1] = ss.y;
        out[sig_off + rbase + 2] = ss.z;
        out[sig_off + rbase + 3] = ss.w;
    }
    // share exact fp32 h via SMEM (reuse xsT area): layout [r][col], conflict-free
    float* hsh = xsT;                      // 4 * 256 * 4B = 4096 B
    hsh[0 * HH + col] = h0;
    hsh[1 * HH + col] = h1;
    hsh[2 * HH + col] = h2;
    hsh[3 * HH + col] = h3;
    __syncthreads();

    // fc1: hid[r][col] = relu(fc1b[col] + sum_k h[r][k] * fc1w[k][col])
    float a0 = fc1b[col], a1 = a0, a2 = a0, a3 = a0;
    #pragma unroll 4
    for (int k = 0; k < HH; k++) {
        const float w = fc1w[k * HH + col];   // coalesced; L2-broadcast across CTAs
        a0 = fmaf(hsh[0 * HH + k], w, a0);
        a1 = fmaf(hsh[1 * HH + k], w, a1);
        a2 = fmaf(hsh[2 * HH + k], w, a2);
        a3 = fmaf(hsh[3 * HH + k], w, a3);
    }
    float* hid = wv;                       // reuse WV area: [r][col] = 4096 B
    hid[0 * HH + col] = fmaxf(a0, 0.0f);
    hid[1 * HH + col] = fmaxf(a1, 0.0f);
    hid[2 * HH + col] = fmaxf(a2, 0.0f);
    hid[3 * HH + col] = fmaxf(a3, 0.0f);
    __syncthreads();

    // fc2 + softplus + vol: 88 threads (r = tid/22, o = tid%22)
    if (tid < RPB * HORZ) {
        const int r = tid / HORZ, o = tid - r * HORZ;
        float u = fc2b[o];
        #pragma unroll 4
        for (int j = 0; j < HH; j++) u = fmaf(hid[r * HH + j], fc2w[j * HORZ + o], u);
        const float sp = (u > 20.0f) ? u : log1pf(expf(u));
        const float ssq = (r == 0) ? ss.x : (r == 1) ? ss.y : (r == 2) ? ss.z : ss.w;
        const float vb = sqrtf(ssq + 1e-8f);
        float v = vb * (1.0f + sp);
        v = fminf(fmaxf(v, 0.01f), 10.0f);
        out[(rbase + r) * HORZ + o] = v;
    }
}

extern "C" void kernel_launch(void* const* d_in, const int* in_sizes, int n_in,
                              void* d_out, int out_size) {
    const float* x    = (const float*)d_in[0];
    const float* Wzw  = (const float*)d_in[1];
    const float* Wzb  = (const float*)d_in[2];
    const float* Uzw  = (const float*)d_in[3];
    const float* Uzb  = (const float*)d_in[4];
    const float* Wrw  = (const float*)d_in[5];
    const float* Wrb  = (const float*)d_in[6];
    const float* Urw  = (const float*)d_in[7];
    const float* Urb  = (const float*)d_in[8];
    const float* Whw  = (const float*)d_in[9];
    const float* Whb  = (const float*)d_in[10];
    const float* Uhw  = (const float*)d_in[11];
    const float* Uhb  = (const float*)d_in[12];
    const float* Wgw  = (const float*)d_in[13];
    const float* Wgb  = (const float*)d_in[14];
    const float* omr  = (const float*)d_in[15];
    const float* alr  = (const float*)d_in[16];
    const float* ber  = (const float*)d_in[17];
    const float* gam  = (const float*)d_in[18];
    const float* fc1w = (const float*)d_in[19];
    const float* fc1b = (const float*)d_in[20];
    const float* fc2w = (const float*)d_in[21];
    const float* fc2b = (const float*)d_in[22];
    float* out = (float*)d_out;
    const int sig_off = out_size - BB;   // vol[B,HOR] then sigma_sq[B]

    cudaFuncSetAttribute(garch_gru_fused,
                         cudaFuncAttributeMaxDynamicSharedMemorySize, SMEM_BYTES);
    garch_gru_fused<<<NCTA, NTH, SMEM_BYTES>>>(
        x, Wzw, Wzb, Uzw, Uzb, Wrw, Wrb, Urw, Urb, Whw, Whb, Uhw, Uhb, Wgw, Wgb,
        omr, alr, ber, gam, fc1w, fc1b, fc2w, fc2b, out, sig_off);
}